// round 2
// baseline (speedup 1.0000x reference)
#include <cuda_runtime.h>

#define DD 128
#define MAXN 100000
#define NBLK_E 1184
#define TPB_E 256
#define WPB 8
#define BN_EPS 1e-5f

typedef unsigned long long u64;

// ---------------- device scratch (no allocation allowed) ----------------
__device__ float g_u[MAXN * DD];                 // x @ W1[:, :128].T   (51.2 MB)
__device__ float g_v[MAXN * DD];                 // x @ W1[:, 128:].T   (51.2 MB)
__device__ float g_part[256 * NBLK_E];           // transposed partials [feat][block]
__device__ float g_sums[256];                    // reduced [sum(128) | sumsq(128)]
__device__ float g_a[DD];                        // BN scale
__device__ float g_c[DD];                        // BN shift
__device__ int   g_idx64;                        // edge_index dtype flag

// ---------------- packed f32x2 helpers (Blackwell FFMA2) ----------------
__device__ __forceinline__ u64 pack2(float a, float b) {
    u64 r; asm("mov.b64 %0, {%1, %2};" : "=l"(r) : "f"(a), "f"(b)); return r;
}
__device__ __forceinline__ void unpack2(u64 p, float& a, float& b) {
    asm("mov.b64 {%0, %1}, %2;" : "=f"(a), "=f"(b) : "l"(p));
}
__device__ __forceinline__ void fma2(u64& d, u64 a, u64 b) {
    asm("fma.rn.f32x2 %0, %1, %2, %0;" : "+l"(d) : "l"(a), "l"(b));
}

// ---------------- dtype detect: int64 edge_index has zero high words ----
__global__ void detect_idx_kernel(const int* __restrict__ ei) {
    int z = 0;
#pragma unroll
    for (int i = 0; i < 16; i++) z |= ei[2 * i + 1];   // high dwords if int64
    g_idx64 = (z == 0) ? 1 : 0;
}

// ---------------- node GEMM: u,v = x @ [W1a|W1b].T ----------------------
// Block = 64 nodes x 256 output features. Thread: 8 nodes x 8 features,
// accumulated as 8x4 packed f32x2 pairs via FFMA2 (2 FMA per fma-pipe issue).
__global__ __launch_bounds__(256) void node_gemm_kernel(
    const float* __restrict__ x, const float* __restrict__ W1, int N) {
    __shared__ float w1s[32 * 260];
    __shared__ float xs[32 * 68];

    const int tid = threadIdx.x;
    const int base = blockIdx.x * 64;
    const int fg = tid & 31;       // feature group: feats fg*8 .. fg*8+7 (of 256)
    const int ng = tid >> 5;       // node group:    nodes ng*8 .. ng*8+7 (of 64)
    const int f0 = fg * 8, n0 = ng * 8;

    u64 acc2[8][4];
#pragma unroll
    for (int n = 0; n < 8; n++)
#pragma unroll
        for (int j = 0; j < 4; j++) acc2[n][j] = 0ull;

    for (int kb = 0; kb < 128; kb += 32) {
        __syncthreads();
        // W1 tile: read coalesced row-major, write transposed [k][f]
#pragma unroll
        for (int it = 0; it < 32; it++) {
            int idx = it * 256 + tid;
            int j = idx >> 6;            // 0..127 (W1 row)
            int cc = idx & 63;
            int kl = cc & 31;
            int half = cc >> 5;          // 0: u-half, 1: v-half
            float val = W1[j * 256 + kb + kl + (half << 7)];
            w1s[kl * 260 + j + (half << 7)] = val;
        }
        // x tile transposed [k][n]
#pragma unroll
        for (int it = 0; it < 8; it++) {
            int idx = it * 256 + tid;
            int n = idx >> 5;
            int kl = idx & 31;
            int node = base + n;
            xs[kl * 68 + n] = (node < N) ? x[node * 128 + kb + kl] : 0.f;
        }
        __syncthreads();
#pragma unroll
        for (int k = 0; k < 32; k++) {
            // w pairs come out of smem already packed (16B aligned)
            const u64* wrow = (const u64*)&w1s[k * 260 + f0];
            u64 w01 = wrow[0], w23 = wrow[1], w45 = wrow[2], w67 = wrow[3];
            float4 xa = *(const float4*)&xs[k * 68 + n0];
            float4 xb = *(const float4*)&xs[k * 68 + n0 + 4];
            u64 xp[8];
            xp[0] = pack2(xa.x, xa.x); xp[1] = pack2(xa.y, xa.y);
            xp[2] = pack2(xa.z, xa.z); xp[3] = pack2(xa.w, xa.w);
            xp[4] = pack2(xb.x, xb.x); xp[5] = pack2(xb.y, xb.y);
            xp[6] = pack2(xb.z, xb.z); xp[7] = pack2(xb.w, xb.w);
#pragma unroll
            for (int n = 0; n < 8; n++) {
                fma2(acc2[n][0], xp[n], w01);
                fma2(acc2[n][1], xp[n], w23);
                fma2(acc2[n][2], xp[n], w45);
                fma2(acc2[n][3], xp[n], w67);
            }
        }
    }

    float* dstbase = (fg < 16) ? g_u : g_v;
    const int fo = (fg < 16) ? f0 : (f0 - 128);
#pragma unroll
    for (int n = 0; n < 8; n++) {
        int node = base + n0 + n;
        if (node < N) {
            float4 o1, o2;
            unpack2(acc2[n][0], o1.x, o1.y);
            unpack2(acc2[n][1], o1.z, o1.w);
            unpack2(acc2[n][2], o2.x, o2.y);
            unpack2(acc2[n][3], o2.z, o2.w);
            *(float4*)&dstbase[node * 128 + fo] = o1;
            *(float4*)&dstbase[node * 128 + fo + 4] = o2;
        }
    }
}

// ---------------- edge pass 1: per-feature sum / sumsq of w=u[s]+v[d] ---
__global__ __launch_bounds__(TPB_E) void edge_stats_kernel(
    const long long* __restrict__ ei, int E, int totalWarps) {
    const int lane = threadIdx.x & 31;
    const int wid = threadIdx.x >> 5;
    const int gw = blockIdx.x * WPB + wid;
    const int is64 = g_idx64;

    float4 s = make_float4(0, 0, 0, 0);
    float4 q = make_float4(0, 0, 0, 0);

#pragma unroll 2
    for (int e = gw; e < E; e += totalWarps) {
        int src, dst;
        if (is64) {
            longlong2 p = ((const longlong2*)ei)[e];
            src = (int)p.x; dst = (int)p.y;
        } else {
            int2 p = ((const int2*)ei)[e];
            src = p.x; dst = p.y;
        }
        float4 uu = *(const float4*)&g_u[src * 128 + lane * 4];
        float4 vv = *(const float4*)&g_v[dst * 128 + lane * 4];
        float w0 = uu.x + vv.x, w1 = uu.y + vv.y, w2 = uu.z + vv.z, w3 = uu.w + vv.w;
        s.x += w0; s.y += w1; s.z += w2; s.w += w3;
        q.x = fmaf(w0, w0, q.x); q.y = fmaf(w1, w1, q.y);
        q.z = fmaf(w2, w2, q.z); q.w = fmaf(w3, w3, q.w);
    }

    __shared__ float red[WPB * 256];
    float* r = red + wid * 256 + lane * 4;
    r[0] = s.x; r[1] = s.y; r[2] = s.z; r[3] = s.w;
    r[128] = q.x; r[129] = q.y; r[130] = q.z; r[131] = q.w;
    __syncthreads();
    int j = threadIdx.x;  // 0..255 (feature slot: sum 0-127, sumsq 128-255)
    float t = 0.f;
#pragma unroll
    for (int w = 0; w < WPB; w++) t += red[w * 256 + j];
    g_part[j * NBLK_E + blockIdx.x] = t;   // transposed: contiguous per feature
}

// ---------------- parallel partial reduction: 256 blocks ----------------
__global__ __launch_bounds__(256) void reduce_partials_kernel() {
    const int j = blockIdx.x;              // feature slot 0..255
    const int t = threadIdx.x;
    float s = 0.f;
    for (int b = t; b < NBLK_E; b += 256) s += g_part[j * NBLK_E + b];
    __shared__ float red[256];
    red[t] = s;
    __syncthreads();
#pragma unroll
    for (int o = 128; o >= 32; o >>= 1) {
        if (t < o) red[t] += red[t + o];
        __syncthreads();
    }
    if (t < 32) {
        float v = red[t];
#pragma unroll
        for (int o = 16; o > 0; o >>= 1) v += __shfl_xor_sync(0xFFFFFFFFu, v, o);
        if (t == 0) g_sums[j] = v;
    }
}

// ---------------- finalize BN affine: a,c (b1 cancels out) --------------
__global__ void finalize_stats_kernel(const float* __restrict__ gamma,
                                      const float* __restrict__ beta,
                                      float invE) {
    int j = threadIdx.x;  // 128 threads
    float mean = g_sums[j] * invE;
    float var = fmaf(-mean, mean, g_sums[128 + j] * invE);
    float a = gamma[j] * rsqrtf(var + BN_EPS);
    g_a[j] = a;
    g_c[j] = fmaf(-a, mean, beta[j]);
}

// ---------------- edge pass 2: out = relu(a*(u+v)+c) @ W2.T + b2 --------
__global__ __launch_bounds__(TPB_E) void edge_out_kernel(
    const long long* __restrict__ ei, const float* __restrict__ W2,
    const float* __restrict__ b2, float* __restrict__ out,
    int E, int totalWarps) {
    const int lane = threadIdx.x & 31;
    const int gw = blockIdx.x * WPB + (threadIdx.x >> 5);
    const int is64 = g_idx64;

    float4 a4 = *(const float4*)&g_a[lane * 4];
    float4 c4 = *(const float4*)&g_c[lane * 4];
    float4 wA = *(const float4*)&W2[lane * 4];
    float4 wB = *(const float4*)&W2[128 + lane * 4];
    float bz0 = b2[0], bz1 = b2[1];

#pragma unroll 2
    for (int e = gw; e < E; e += totalWarps) {
        int src, dst;
        if (is64) {
            longlong2 p = ((const longlong2*)ei)[e];
            src = (int)p.x; dst = (int)p.y;
        } else {
            int2 p = ((const int2*)ei)[e];
            src = p.x; dst = p.y;
        }
        float4 uu = *(const float4*)&g_u[src * 128 + lane * 4];
        float4 vv = *(const float4*)&g_v[dst * 128 + lane * 4];
        float r0 = fmaxf(fmaf(a4.x, uu.x + vv.x, c4.x), 0.f);
        float r1 = fmaxf(fmaf(a4.y, uu.y + vv.y, c4.y), 0.f);
        float r2 = fmaxf(fmaf(a4.z, uu.z + vv.z, c4.z), 0.f);
        float r3 = fmaxf(fmaf(a4.w, uu.w + vv.w, c4.w), 0.f);
        float p0 = r0 * wA.x + r1 * wA.y + r2 * wA.z + r3 * wA.w;
        float p1 = r0 * wB.x + r1 * wB.y + r2 * wB.z + r3 * wB.w;
#pragma unroll
        for (int o = 16; o > 0; o >>= 1) {
            p0 += __shfl_xor_sync(0xFFFFFFFFu, p0, o);
            p1 += __shfl_xor_sync(0xFFFFFFFFu, p1, o);
        }
        if (lane == 0)
            ((float2*)out)[e] = make_float2(p0 + bz0, p1 + bz1);
    }
}

// ---------------- launch ------------------------------------------------
extern "C" void kernel_launch(void* const* d_in, const int* in_sizes, int n_in,
                              void* d_out, int out_size) {
    const float* x = (const float*)d_in[0];
    const long long* ei = (const long long*)d_in[1];
    const float* W1 = (const float*)d_in[2];
    // d_in[3] = b1 : cancels inside BatchNorm, unused
    const float* gamma = (const float*)d_in[4];
    const float* beta = (const float*)d_in[5];
    const float* W2 = (const float*)d_in[6];
    const float* b2 = (const float*)d_in[7];

    const int N = in_sizes[0] / DD;
    const int E = in_sizes[1] / 2;
    const int totalWarps = NBLK_E * WPB;

    detect_idx_kernel<<<1, 1>>>((const int*)ei);
    node_gemm_kernel<<<(N + 63) / 64, 256>>>(x, W1, N);
    edge_stats_kernel<<<NBLK_E, TPB_E>>>(ei, E, totalWarps);
    reduce_partials_kernel<<<256, 256>>>();
    finalize_stats_kernel<<<1, 128>>>(gamma, beta, 1.0f / (float)E);
    edge_out_kernel<<<NBLK_E, TPB_E>>>(ei, W2, b2, (float*)d_out, E, totalWarps);
}

// round 3
// speedup vs baseline: 1.1196x; 1.1196x over previous
#include <cuda_runtime.h>
#include <cuda_fp16.h>

#define DD 128
#define MAXN 100000
#define NBLK_E 1184
#define TPB_E 256
#define WPB 8
#define BN_EPS 1e-5f

// ---------------- device scratch (no allocation allowed) ----------------
__device__ __half g_u[MAXN * DD];                // x @ W1[:, :128].T  (25.6 MB, fp16)
__device__ __half g_v[MAXN * DD];                // x @ W1[:, 128:].T  (25.6 MB, fp16)
__device__ float g_part[256 * NBLK_E];           // transposed partials [feat][block]
__device__ float g_sums[256];                    // reduced [sum(128) | sumsq(128)]
__device__ float g_a[DD];                        // BN scale
__device__ float g_c[DD];                        // BN shift
__device__ int   g_idx64;                        // edge_index dtype flag

// ---------------- dtype detect: int64 edge_index has zero high words ----
__global__ void detect_idx_kernel(const int* __restrict__ ei) {
    int z = 0;
#pragma unroll
    for (int i = 0; i < 16; i++) z |= ei[2 * i + 1];   // high dwords if int64
    g_idx64 = (z == 0) ? 1 : 0;
}

// ---------------- node GEMM: u,v = x @ [W1a|W1b].T  (fp32 math, fp16 out)
// Block = 64 nodes x 256 output features. Thread: 8 nodes x 8 features.
// (reverted to round-1 plain-FFMA form; FFMA2 variant spilled registers)
__global__ __launch_bounds__(256) void node_gemm_kernel(
    const float* __restrict__ x, const float* __restrict__ W1, int N) {
    __shared__ float w1s[32 * 260];
    __shared__ float xs[32 * 68];

    const int tid = threadIdx.x;
    const int base = blockIdx.x * 64;
    const int fg = tid & 31;       // feature group: feats fg*8 .. fg*8+7 (of 256)
    const int ng = tid >> 5;       // node group:    nodes ng*8 .. ng*8+7 (of 64)
    const int f0 = fg * 8, n0 = ng * 8;

    float acc[8][8];
#pragma unroll
    for (int n = 0; n < 8; n++)
#pragma unroll
        for (int f = 0; f < 8; f++) acc[n][f] = 0.f;

    for (int kb = 0; kb < 128; kb += 32) {
        __syncthreads();
        // W1 tile: read coalesced row-major, write transposed [k][f]
#pragma unroll
        for (int it = 0; it < 32; it++) {
            int idx = it * 256 + tid;
            int j = idx >> 6;            // 0..127 (W1 row)
            int cc = idx & 63;
            int kl = cc & 31;
            int half = cc >> 5;          // 0: u-half, 1: v-half
            float val = W1[j * 256 + kb + kl + (half << 7)];
            w1s[kl * 260 + j + (half << 7)] = val;
        }
        // x tile transposed [k][n]
#pragma unroll
        for (int it = 0; it < 8; it++) {
            int idx = it * 256 + tid;
            int n = idx >> 5;
            int kl = idx & 31;
            int node = base + n;
            xs[kl * 68 + n] = (node < N) ? x[node * 128 + kb + kl] : 0.f;
        }
        __syncthreads();
#pragma unroll
        for (int k = 0; k < 32; k++) {
            float4 wa = *(const float4*)&w1s[k * 260 + f0];
            float4 wb = *(const float4*)&w1s[k * 260 + f0 + 4];
            float4 xa = *(const float4*)&xs[k * 68 + n0];
            float4 xb = *(const float4*)&xs[k * 68 + n0 + 4];
            float wv[8] = {wa.x, wa.y, wa.z, wa.w, wb.x, wb.y, wb.z, wb.w};
            float xv[8] = {xa.x, xa.y, xa.z, xa.w, xb.x, xb.y, xb.z, xb.w};
#pragma unroll
            for (int n = 0; n < 8; n++)
#pragma unroll
                for (int f = 0; f < 8; f++)
                    acc[n][f] = fmaf(xv[n], wv[f], acc[n][f]);
        }
    }

    __half* dstbase = (fg < 16) ? g_u : g_v;
    const int fo = (fg < 16) ? f0 : (f0 - 128);
#pragma unroll
    for (int n = 0; n < 8; n++) {
        int node = base + n0 + n;
        if (node < N) {
            __half2 h0 = __floats2half2_rn(acc[n][0], acc[n][1]);
            __half2 h1 = __floats2half2_rn(acc[n][2], acc[n][3]);
            __half2 h2 = __floats2half2_rn(acc[n][4], acc[n][5]);
            __half2 h3 = __floats2half2_rn(acc[n][6], acc[n][7]);
            uint4 o;
            o.x = *(unsigned int*)&h0;
            o.y = *(unsigned int*)&h1;
            o.z = *(unsigned int*)&h2;
            o.w = *(unsigned int*)&h3;
            *(uint4*)&dstbase[node * 128 + fo] = o;   // 16B aligned (fo % 8 == 0)
        }
    }
}

// ---------------- edge pass 1: per-feature sum / sumsq of w=u[s]+v[d] ---
__global__ __launch_bounds__(TPB_E) void edge_stats_kernel(
    const long long* __restrict__ ei, int E, int totalWarps) {
    const int lane = threadIdx.x & 31;
    const int wid = threadIdx.x >> 5;
    const int gw = blockIdx.x * WPB + wid;
    const int is64 = g_idx64;

    float4 s = make_float4(0, 0, 0, 0);
    float4 q = make_float4(0, 0, 0, 0);

#pragma unroll 2
    for (int e = gw; e < E; e += totalWarps) {
        int src, dst;
        if (is64) {
            longlong2 p = ((const longlong2*)ei)[e];
            src = (int)p.x; dst = (int)p.y;
        } else {
            int2 p = ((const int2*)ei)[e];
            src = p.x; dst = p.y;
        }
        uint2 ur = *(const uint2*)&g_u[src * 128 + lane * 4];
        uint2 vr = *(const uint2*)&g_v[dst * 128 + lane * 4];
        float2 u0 = __half22float2(*(__half2*)&ur.x);
        float2 u1 = __half22float2(*(__half2*)&ur.y);
        float2 v0 = __half22float2(*(__half2*)&vr.x);
        float2 v1 = __half22float2(*(__half2*)&vr.y);
        float w0 = u0.x + v0.x, w1 = u0.y + v0.y;
        float w2 = u1.x + v1.x, w3 = u1.y + v1.y;
        s.x += w0; s.y += w1; s.z += w2; s.w += w3;
        q.x = fmaf(w0, w0, q.x); q.y = fmaf(w1, w1, q.y);
        q.z = fmaf(w2, w2, q.z); q.w = fmaf(w3, w3, q.w);
    }

    __shared__ float red[WPB * 256];
    float* r = red + wid * 256 + lane * 4;
    r[0] = s.x; r[1] = s.y; r[2] = s.z; r[3] = s.w;
    r[128] = q.x; r[129] = q.y; r[130] = q.z; r[131] = q.w;
    __syncthreads();
    int j = threadIdx.x;  // 0..255 (feature slot: sum 0-127, sumsq 128-255)
    float t = 0.f;
#pragma unroll
    for (int w = 0; w < WPB; w++) t += red[w * 256 + j];
    g_part[j * NBLK_E + blockIdx.x] = t;   // transposed: contiguous per feature
}

// ---------------- parallel partial reduction: 256 blocks ----------------
__global__ __launch_bounds__(256) void reduce_partials_kernel() {
    const int j = blockIdx.x;              // feature slot 0..255
    const int t = threadIdx.x;
    float s = 0.f;
    for (int b = t; b < NBLK_E; b += 256) s += g_part[j * NBLK_E + b];
    __shared__ float red[256];
    red[t] = s;
    __syncthreads();
#pragma unroll
    for (int o = 128; o >= 32; o >>= 1) {
        if (t < o) red[t] += red[t + o];
        __syncthreads();
    }
    if (t < 32) {
        float v = red[t];
#pragma unroll
        for (int o = 16; o > 0; o >>= 1) v += __shfl_xor_sync(0xFFFFFFFFu, v, o);
        if (t == 0) g_sums[j] = v;
    }
}

// ---------------- finalize BN affine: a,c (b1 cancels out) --------------
__global__ void finalize_stats_kernel(const float* __restrict__ gamma,
                                      const float* __restrict__ beta,
                                      float invE) {
    int j = threadIdx.x;  // 128 threads
    float mean = g_sums[j] * invE;
    float var = fmaf(-mean, mean, g_sums[128 + j] * invE);
    float a = gamma[j] * rsqrtf(var + BN_EPS);
    g_a[j] = a;
    g_c[j] = fmaf(-a, mean, beta[j]);
}

// ---------------- edge pass 2: out = relu(a*(u+v)+c) @ W2.T + b2 --------
__global__ __launch_bounds__(TPB_E) void edge_out_kernel(
    const long long* __restrict__ ei, const float* __restrict__ W2,
    const float* __restrict__ b2, float* __restrict__ out,
    int E, int totalWarps) {
    const int lane = threadIdx.x & 31;
    const int gw = blockIdx.x * WPB + (threadIdx.x >> 5);
    const int is64 = g_idx64;

    float4 a4 = *(const float4*)&g_a[lane * 4];
    float4 c4 = *(const float4*)&g_c[lane * 4];
    float4 wA = *(const float4*)&W2[lane * 4];
    float4 wB = *(const float4*)&W2[128 + lane * 4];
    float bz0 = b2[0], bz1 = b2[1];

#pragma unroll 2
    for (int e = gw; e < E; e += totalWarps) {
        int src, dst;
        if (is64) {
            longlong2 p = ((const longlong2*)ei)[e];
            src = (int)p.x; dst = (int)p.y;
        } else {
            int2 p = ((const int2*)ei)[e];
            src = p.x; dst = p.y;
        }
        uint2 ur = *(const uint2*)&g_u[src * 128 + lane * 4];
        uint2 vr = *(const uint2*)&g_v[dst * 128 + lane * 4];
        float2 u0 = __half22float2(*(__half2*)&ur.x);
        float2 u1 = __half22float2(*(__half2*)&ur.y);
        float2 v0 = __half22float2(*(__half2*)&vr.x);
        float2 v1 = __half22float2(*(__half2*)&vr.y);
        float r0 = fmaxf(fmaf(a4.x, u0.x + v0.x, c4.x), 0.f);
        float r1 = fmaxf(fmaf(a4.y, u0.y + v0.y, c4.y), 0.f);
        float r2 = fmaxf(fmaf(a4.z, u1.x + v1.x, c4.z), 0.f);
        float r3 = fmaxf(fmaf(a4.w, u1.y + v1.y, c4.w), 0.f);
        float p0 = r0 * wA.x + r1 * wA.y + r2 * wA.z + r3 * wA.w;
        float p1 = r0 * wB.x + r1 * wB.y + r2 * wB.z + r3 * wB.w;
#pragma unroll
        for (int o = 16; o > 0; o >>= 1) {
            p0 += __shfl_xor_sync(0xFFFFFFFFu, p0, o);
            p1 += __shfl_xor_sync(0xFFFFFFFFu, p1, o);
        }
        if (lane == 0)
            ((float2*)out)[e] = make_float2(p0 + bz0, p1 + bz1);
    }
}

// ---------------- launch ------------------------------------------------
extern "C" void kernel_launch(void* const* d_in, const int* in_sizes, int n_in,
                              void* d_out, int out_size) {
    const float* x = (const float*)d_in[0];
    const long long* ei = (const long long*)d_in[1];
    const float* W1 = (const float*)d_in[2];
    // d_in[3] = b1 : cancels inside BatchNorm, unused
    const float* gamma = (const float*)d_in[4];
    const float* beta = (const float*)d_in[5];
    const float* W2 = (const float*)d_in[6];
    const float* b2 = (const float*)d_in[7];

    const int N = in_sizes[0] / DD;
    const int E = in_sizes[1] / 2;
    const int totalWarps = NBLK_E * WPB;

    detect_idx_kernel<<<1, 1>>>((const int*)ei);
    node_gemm_kernel<<<(N + 63) / 64, 256>>>(x, W1, N);
    edge_stats_kernel<<<NBLK_E, TPB_E>>>(ei, E, totalWarps);
    reduce_partials_kernel<<<256, 256>>>();
    finalize_stats_kernel<<<1, 128>>>(gamma, beta, 1.0f / (float)E);
    edge_out_kernel<<<NBLK_E, TPB_E>>>(ei, W2, b2, (float*)d_out, E, totalWarps);
}

// round 4
// speedup vs baseline: 1.7071x; 1.5248x over previous
#include <cuda_runtime.h>
#include <cuda_fp16.h>
#include <mma.h>
using namespace nvcuda;

#define DD 128
#define MAXN 100000
#define NBLK_E 1184
#define TPB_E 256
#define WPB 8
#define BN_EPS 1e-5f

// ---------------- device scratch (no allocation allowed) ----------------
__device__ __half g_u[MAXN * DD];                // node proj, u-half (25.6 MB)
__device__ __half g_v[MAXN * DD];                // node proj, v-half (25.6 MB)
__device__ __half g_xh[MAXN * DD];               // x in fp16 (25.6 MB)
__device__ __half g_w1h[128 * 256];              // W1 fused [k][out] fp16
__device__ float g_part[256 * NBLK_E];           // transposed partials [feat][block]
__device__ float g_sums[256];                    // reduced [sum(128) | sumsq(128)]
__device__ float g_a[DD];                        // BN scale
__device__ float g_c[DD];                        // BN shift
__device__ int   g_idx64;                        // edge_index dtype flag

// ---------------- dtype detect: int64 edge_index has zero high words ----
__global__ void detect_idx_kernel(const int* __restrict__ ei) {
    int z = 0;
#pragma unroll
    for (int i = 0; i < 16; i++) z |= ei[2 * i + 1];
    g_idx64 = (z == 0) ? 1 : 0;
}

// ---------------- prep: x -> fp16 ---------------------------------------
__global__ __launch_bounds__(256) void x_to_half_kernel(
    const float* __restrict__ x, int total4) {
    int i = blockIdx.x * 256 + threadIdx.x;
    if (i < total4) {
        float4 f = ((const float4*)x)[i];
        __half2 a = __floats2half2_rn(f.x, f.y);
        __half2 b = __floats2half2_rn(f.z, f.w);
        uint2 o;
        o.x = *(unsigned int*)&a;
        o.y = *(unsigned int*)&b;
        ((uint2*)g_xh)[i] = o;
    }
}

// ---------------- prep: W1 -> fused fp16 [k 0..127][o 0..255] -----------
// o<128: W1[o, k] (u-half); o>=128: W1[o-128, 128+k] (v-half)
__global__ __launch_bounds__(256) void prep_w1_kernel(const float* __restrict__ W1) {
    int idx = blockIdx.x * 256 + threadIdx.x;
    if (idx < 128 * 256) {
        int k = idx >> 8, o = idx & 255;
        float val = (o < 128) ? W1[o * 256 + k] : W1[(o - 128) * 256 + 128 + k];
        g_w1h[k * 256 + o] = __float2half(val);
    }
}

// ---------------- node GEMM via tensor cores (wmma fp16, fp32 accum) ----
// Block: 128 nodes x 64 out-feats. 8 warps = 4(n) x 2(f); warp = 32x32.
// K chunked by 64. smem reused as fp32 staging for the fp16 epilogue.
#define A_LD 72
#define B_LD 72
#define S_LD 36
__global__ __launch_bounds__(256) void node_gemm_mma_kernel(int N) {
    __shared__ char raw[8 * 32 * S_LD * 4];      // 36,864 B (>= tiles: 27,648 B)
    __half (*As)[A_LD] = (__half(*)[A_LD])raw;               // [128][72]
    __half (*Bs)[B_LD] = (__half(*)[B_LD])(raw + 128 * A_LD * 2); // [64][72]

    const int tid = threadIdx.x;
    const int warp = tid >> 5;
    const int lane = tid & 31;
    const int base = blockIdx.x * 128;
    const int fblk = blockIdx.y;                 // 0..3 (64-feat tile)
    const int wr = warp >> 1;                    // warp node-row 0..3
    const int wc = warp & 1;                     // warp feat-col 0..1

    wmma::fragment<wmma::accumulator, 16, 16, 16, float> acc[2][2];
#pragma unroll
    for (int r = 0; r < 2; r++)
#pragma unroll
        for (int c = 0; c < 2; c++) wmma::fill_fragment(acc[r][c], 0.f);

    for (int kc = 0; kc < 128; kc += 64) {
        __syncthreads();
        // A tile: 128 nodes x 64 k (8192 halfs = 2048 uint2)
#pragma unroll
        for (int it = 0; it < 8; it++) {
            int idx = it * 256 + tid;
            int r = idx >> 4;                    // 16 uint2 per row
            int c4 = idx & 15;
            int node = base + r;
            uint2 val = (node < N) ? ((const uint2*)&g_xh[node * 128 + kc])[c4]
                                   : make_uint2(0u, 0u);
            *(uint2*)&As[r][c4 * 4] = val;
        }
        // B tile: 64 k x 64 f (4096 halfs = 1024 uint2)
#pragma unroll
        for (int it = 0; it < 4; it++) {
            int idx = it * 256 + tid;
            int r = idx >> 4;
            int c4 = idx & 15;
            uint2 val = ((const uint2*)&g_w1h[(kc + r) * 256 + fblk * 64])[c4];
            *(uint2*)&Bs[r][c4 * 4] = val;
        }
        __syncthreads();
#pragma unroll
        for (int ks = 0; ks < 64; ks += 16) {
            wmma::fragment<wmma::matrix_a, 16, 16, 16, __half, wmma::row_major> af[2];
            wmma::fragment<wmma::matrix_b, 16, 16, 16, __half, wmma::row_major> bf[2];
            wmma::load_matrix_sync(af[0], &As[wr * 32][ks], A_LD);
            wmma::load_matrix_sync(af[1], &As[wr * 32 + 16][ks], A_LD);
            wmma::load_matrix_sync(bf[0], &Bs[ks][wc * 32], B_LD);
            wmma::load_matrix_sync(bf[1], &Bs[ks][wc * 32 + 16], B_LD);
#pragma unroll
            for (int r = 0; r < 2; r++)
#pragma unroll
                for (int c = 0; c < 2; c++)
                    wmma::mma_sync(acc[r][c], af[r], bf[c], acc[r][c]);
        }
    }

    // Epilogue: stage fp32 in smem, convert to fp16, write g_u / g_v
    __syncthreads();
    float (*stg)[S_LD] = (float(*)[S_LD])(raw + warp * 32 * S_LD * 4);  // [32][36]
#pragma unroll
    for (int r = 0; r < 2; r++)
#pragma unroll
        for (int c = 0; c < 2; c++)
            wmma::store_matrix_sync(&stg[r * 16][c * 16], acc[r][c], S_LD,
                                    wmma::mem_row_major);
    __syncwarp();

    const int node = base + wr * 32 + lane;
    if (node < N) {
        const int o0 = fblk * 64 + wc * 32;          // global out-feature base
        __half* dst = (o0 < 128) ? &g_u[node * 128 + o0]
                                 : &g_v[node * 128 + (o0 - 128)];
        const float* srow = stg[lane];
#pragma unroll
        for (int c = 0; c < 32; c += 8) {
            __half2 h0 = __floats2half2_rn(srow[c + 0], srow[c + 1]);
            __half2 h1 = __floats2half2_rn(srow[c + 2], srow[c + 3]);
            __half2 h2 = __floats2half2_rn(srow[c + 4], srow[c + 5]);
            __half2 h3 = __floats2half2_rn(srow[c + 6], srow[c + 7]);
            uint4 o;
            o.x = *(unsigned int*)&h0;
            o.y = *(unsigned int*)&h1;
            o.z = *(unsigned int*)&h2;
            o.w = *(unsigned int*)&h3;
            *(uint4*)&dst[c] = o;
        }
    }
}

// ---------------- edge pass 1: per-feature sum / sumsq of w=u[s]+v[d] ---
__global__ __launch_bounds__(TPB_E) void edge_stats_kernel(
    const long long* __restrict__ ei, int E, int totalWarps) {
    const int lane = threadIdx.x & 31;
    const int wid = threadIdx.x >> 5;
    const int gw = blockIdx.x * WPB + wid;
    const int is64 = g_idx64;

    float4 s = make_float4(0, 0, 0, 0);
    float4 q = make_float4(0, 0, 0, 0);

#pragma unroll 2
    for (int e = gw; e < E; e += totalWarps) {
        int src, dst;
        if (is64) {
            longlong2 p = ((const longlong2*)ei)[e];
            src = (int)p.x; dst = (int)p.y;
        } else {
            int2 p = ((const int2*)ei)[e];
            src = p.x; dst = p.y;
        }
        uint2 ur = *(const uint2*)&g_u[src * 128 + lane * 4];
        uint2 vr = *(const uint2*)&g_v[dst * 128 + lane * 4];
        float2 u0 = __half22float2(*(__half2*)&ur.x);
        float2 u1 = __half22float2(*(__half2*)&ur.y);
        float2 v0 = __half22float2(*(__half2*)&vr.x);
        float2 v1 = __half22float2(*(__half2*)&vr.y);
        float w0 = u0.x + v0.x, w1 = u0.y + v0.y;
        float w2 = u1.x + v1.x, w3 = u1.y + v1.y;
        s.x += w0; s.y += w1; s.z += w2; s.w += w3;
        q.x = fmaf(w0, w0, q.x); q.y = fmaf(w1, w1, q.y);
        q.z = fmaf(w2, w2, q.z); q.w = fmaf(w3, w3, q.w);
    }

    __shared__ float red[WPB * 256];
    float* r = red + wid * 256 + lane * 4;
    r[0] = s.x; r[1] = s.y; r[2] = s.z; r[3] = s.w;
    r[128] = q.x; r[129] = q.y; r[130] = q.z; r[131] = q.w;
    __syncthreads();
    int j = threadIdx.x;
    float t = 0.f;
#pragma unroll
    for (int w = 0; w < WPB; w++) t += red[w * 256 + j];
    g_part[j * NBLK_E + blockIdx.x] = t;
}

// ---------------- parallel partial reduction: 256 blocks ----------------
__global__ __launch_bounds__(256) void reduce_partials_kernel() {
    const int j = blockIdx.x;
    const int t = threadIdx.x;
    float s = 0.f;
    for (int b = t; b < NBLK_E; b += 256) s += g_part[j * NBLK_E + b];
    __shared__ float red[256];
    red[t] = s;
    __syncthreads();
#pragma unroll
    for (int o = 128; o >= 32; o >>= 1) {
        if (t < o) red[t] += red[t + o];
        __syncthreads();
    }
    if (t < 32) {
        float v = red[t];
#pragma unroll
        for (int o = 16; o > 0; o >>= 1) v += __shfl_xor_sync(0xFFFFFFFFu, v, o);
        if (t == 0) g_sums[j] = v;
    }
}

// ---------------- finalize BN affine: a,c (b1 cancels out) --------------
__global__ void finalize_stats_kernel(const float* __restrict__ gamma,
                                      const float* __restrict__ beta,
                                      float invE) {
    int j = threadIdx.x;
    float mean = g_sums[j] * invE;
    float var = fmaf(-mean, mean, g_sums[128 + j] * invE);
    float a = gamma[j] * rsqrtf(var + BN_EPS);
    g_a[j] = a;
    g_c[j] = fmaf(-a, mean, beta[j]);
}

// ---------------- edge pass 2: out = relu(a*(u+v)+c) @ W2.T + b2 --------
__global__ __launch_bounds__(TPB_E) void edge_out_kernel(
    const long long* __restrict__ ei, const float* __restrict__ W2,
    const float* __restrict__ b2, float* __restrict__ out,
    int E, int totalWarps) {
    const int lane = threadIdx.x & 31;
    const int gw = blockIdx.x * WPB + (threadIdx.x >> 5);
    const int is64 = g_idx64;

    float4 a4 = *(const float4*)&g_a[lane * 4];
    float4 c4 = *(const float4*)&g_c[lane * 4];
    float4 wA = *(const float4*)&W2[lane * 4];
    float4 wB = *(const float4*)&W2[128 + lane * 4];
    float bz0 = b2[0], bz1 = b2[1];

#pragma unroll 2
    for (int e = gw; e < E; e += totalWarps) {
        int src, dst;
        if (is64) {
            longlong2 p = ((const longlong2*)ei)[e];
            src = (int)p.x; dst = (int)p.y;
        } else {
            int2 p = ((const int2*)ei)[e];
            src = p.x; dst = p.y;
        }
        uint2 ur = *(const uint2*)&g_u[src * 128 + lane * 4];
        uint2 vr = *(const uint2*)&g_v[dst * 128 + lane * 4];
        float2 u0 = __half22float2(*(__half2*)&ur.x);
        float2 u1 = __half22float2(*(__half2*)&ur.y);
        float2 v0 = __half22float2(*(__half2*)&vr.x);
        float2 v1 = __half22float2(*(__half2*)&vr.y);
        float r0 = fmaxf(fmaf(a4.x, u0.x + v0.x, c4.x), 0.f);
        float r1 = fmaxf(fmaf(a4.y, u0.y + v0.y, c4.y), 0.f);
        float r2 = fmaxf(fmaf(a4.z, u1.x + v1.x, c4.z), 0.f);
        float r3 = fmaxf(fmaf(a4.w, u1.y + v1.y, c4.w), 0.f);
        float p0 = r0 * wA.x + r1 * wA.y + r2 * wA.z + r3 * wA.w;
        float p1 = r0 * wB.x + r1 * wB.y + r2 * wB.z + r3 * wB.w;
#pragma unroll
        for (int o = 16; o > 0; o >>= 1) {
            p0 += __shfl_xor_sync(0xFFFFFFFFu, p0, o);
            p1 += __shfl_xor_sync(0xFFFFFFFFu, p1, o);
        }
        if (lane == 0)
            ((float2*)out)[e] = make_float2(p0 + bz0, p1 + bz1);
    }
}

// ---------------- launch ------------------------------------------------
extern "C" void kernel_launch(void* const* d_in, const int* in_sizes, int n_in,
                              void* d_out, int out_size) {
    const float* x = (const float*)d_in[0];
    const long long* ei = (const long long*)d_in[1];
    const float* W1 = (const float*)d_in[2];
    // d_in[3] = b1 : cancels inside BatchNorm, unused
    const float* gamma = (const float*)d_in[4];
    const float* beta = (const float*)d_in[5];
    const float* W2 = (const float*)d_in[6];
    const float* b2 = (const float*)d_in[7];

    const int N = in_sizes[0] / DD;
    const int E = in_sizes[1] / 2;
    const int totalWarps = NBLK_E * WPB;
    const int total4 = N * DD / 4;

    detect_idx_kernel<<<1, 1>>>((const int*)ei);
    x_to_half_kernel<<<(total4 + 255) / 256, 256>>>(x, total4);
    prep_w1_kernel<<<128, 256>>>(W1);
    dim3 ggrid((N + 127) / 128, 4);
    node_gemm_mma_kernel<<<ggrid, 256>>>(N);
    edge_stats_kernel<<<NBLK_E, TPB_E>>>(ei, E, totalWarps);
    reduce_partials_kernel<<<256, 256>>>();
    finalize_stats_kernel<<<1, 128>>>(gamma, beta, 1.0f / (float)E);
    edge_out_kernel<<<NBLK_E, TPB_E>>>(ei, W2, b2, (float*)d_out, E, totalWarps);
}

// round 5
// speedup vs baseline: 1.7619x; 1.0321x over previous
#include <cuda_runtime.h>
#include <cuda_fp16.h>
#include <mma.h>
using namespace nvcuda;

#define DD 128
#define MAXN 100000
#define MAXE 1000000
#define NBLK_S 592
#define NBLK_O 444
#define TPB_E 256
#define WPB 8
#define BN_EPS 1e-5f

// ---------------- device scratch (no allocation allowed) ----------------
__device__ __half g_u[MAXN * DD];                // node proj, u-half (25.6 MB)
__device__ __half g_v[MAXN * DD];                // node proj, v-half (25.6 MB)
__device__ __half g_xh[MAXN * DD];               // x in fp16 (25.6 MB)
__device__ __half g_w1h[128 * 256];              // W1 fused [k][out] fp16
__device__ int2  g_ei32[MAXE];                   // edge index as int32 (8 MB)
__device__ float g_part[256 * NBLK_S];           // transposed partials [feat][block]
__device__ float g_sums[256];                    // reduced [sum(128) | sumsq(128)]
__device__ float g_a[DD];                        // BN scale
__device__ float g_c[DD];                        // BN shift
__device__ int   g_idx64;                        // edge_index dtype flag

// ---------------- dtype detect: int64 edge_index has zero high words ----
__global__ void detect_idx_kernel(const int* __restrict__ ei) {
    int z = 0;
#pragma unroll
    for (int i = 0; i < 16; i++) z |= ei[2 * i + 1];
    g_idx64 = (z == 0) ? 1 : 0;
}

// ---------------- prep: edge index -> int32 ------------------------------
__global__ __launch_bounds__(256) void convert_idx_kernel(
    const long long* __restrict__ ei, int E) {
    int e = blockIdx.x * 256 + threadIdx.x;
    if (e >= E) return;
    int2 o;
    if (g_idx64) {
        longlong2 p = ((const longlong2*)ei)[e];
        o = make_int2((int)p.x, (int)p.y);
    } else {
        o = ((const int2*)ei)[e];
    }
    g_ei32[e] = o;
}

// ---------------- prep: x -> fp16 ---------------------------------------
__global__ __launch_bounds__(256) void x_to_half_kernel(
    const float* __restrict__ x, int total4) {
    int i = blockIdx.x * 256 + threadIdx.x;
    if (i < total4) {
        float4 f = ((const float4*)x)[i];
        __half2 a = __floats2half2_rn(f.x, f.y);
        __half2 b = __floats2half2_rn(f.z, f.w);
        uint2 o;
        o.x = *(unsigned int*)&a;
        o.y = *(unsigned int*)&b;
        ((uint2*)g_xh)[i] = o;
    }
}

// ---------------- prep: W1 -> fused fp16 [k 0..127][o 0..255] -----------
__global__ __launch_bounds__(256) void prep_w1_kernel(const float* __restrict__ W1) {
    int idx = blockIdx.x * 256 + threadIdx.x;
    if (idx < 128 * 256) {
        int k = idx >> 8, o = idx & 255;
        float val = (o < 128) ? W1[o * 256 + k] : W1[(o - 128) * 256 + 128 + k];
        g_w1h[k * 256 + o] = __float2half(val);
    }
}

// ---------------- node GEMM via tensor cores (wmma fp16, fp32 accum) ----
#define A_LD 72
#define B_LD 72
#define S_LD 36
__global__ __launch_bounds__(256) void node_gemm_mma_kernel(int N) {
    __shared__ char raw[8 * 32 * S_LD * 4];
    __half (*As)[A_LD] = (__half(*)[A_LD])raw;
    __half (*Bs)[B_LD] = (__half(*)[B_LD])(raw + 128 * A_LD * 2);

    const int tid = threadIdx.x;
    const int warp = tid >> 5;
    const int lane = tid & 31;
    const int base = blockIdx.x * 128;
    const int fblk = blockIdx.y;
    const int wr = warp >> 1;
    const int wc = warp & 1;

    wmma::fragment<wmma::accumulator, 16, 16, 16, float> acc[2][2];
#pragma unroll
    for (int r = 0; r < 2; r++)
#pragma unroll
        for (int c = 0; c < 2; c++) wmma::fill_fragment(acc[r][c], 0.f);

    for (int kc = 0; kc < 128; kc += 64) {
        __syncthreads();
#pragma unroll
        for (int it = 0; it < 8; it++) {
            int idx = it * 256 + tid;
            int r = idx >> 4;
            int c4 = idx & 15;
            int node = base + r;
            uint2 val = (node < N) ? ((const uint2*)&g_xh[node * 128 + kc])[c4]
                                   : make_uint2(0u, 0u);
            *(uint2*)&As[r][c4 * 4] = val;
        }
#pragma unroll
        for (int it = 0; it < 4; it++) {
            int idx = it * 256 + tid;
            int r = idx >> 4;
            int c4 = idx & 15;
            uint2 val = ((const uint2*)&g_w1h[(kc + r) * 256 + fblk * 64])[c4];
            *(uint2*)&Bs[r][c4 * 4] = val;
        }
        __syncthreads();
#pragma unroll
        for (int ks = 0; ks < 64; ks += 16) {
            wmma::fragment<wmma::matrix_a, 16, 16, 16, __half, wmma::row_major> af[2];
            wmma::fragment<wmma::matrix_b, 16, 16, 16, __half, wmma::row_major> bf[2];
            wmma::load_matrix_sync(af[0], &As[wr * 32][ks], A_LD);
            wmma::load_matrix_sync(af[1], &As[wr * 32 + 16][ks], A_LD);
            wmma::load_matrix_sync(bf[0], &Bs[ks][wc * 32], B_LD);
            wmma::load_matrix_sync(bf[1], &Bs[ks][wc * 32 + 16], B_LD);
#pragma unroll
            for (int r = 0; r < 2; r++)
#pragma unroll
                for (int c = 0; c < 2; c++)
                    wmma::mma_sync(acc[r][c], af[r], bf[c], acc[r][c]);
        }
    }

    __syncthreads();
    float (*stg)[S_LD] = (float(*)[S_LD])(raw + warp * 32 * S_LD * 4);
#pragma unroll
    for (int r = 0; r < 2; r++)
#pragma unroll
        for (int c = 0; c < 2; c++)
            wmma::store_matrix_sync(&stg[r * 16][c * 16], acc[r][c], S_LD,
                                    wmma::mem_row_major);
    __syncwarp();

    const int node = base + wr * 32 + lane;
    if (node < N) {
        const int o0 = fblk * 64 + wc * 32;
        __half* dst = (o0 < 128) ? &g_u[node * 128 + o0]
                                 : &g_v[node * 128 + (o0 - 128)];
        const float* srow = stg[lane];
#pragma unroll
        for (int c = 0; c < 32; c += 8) {
            __half2 h0 = __floats2half2_rn(srow[c + 0], srow[c + 1]);
            __half2 h1 = __floats2half2_rn(srow[c + 2], srow[c + 3]);
            __half2 h2 = __floats2half2_rn(srow[c + 4], srow[c + 5]);
            __half2 h3 = __floats2half2_rn(srow[c + 6], srow[c + 7]);
            uint4 o;
            o.x = *(unsigned int*)&h0;
            o.y = *(unsigned int*)&h1;
            o.z = *(unsigned int*)&h2;
            o.w = *(unsigned int*)&h3;
            *(uint4*)&dst[c] = o;
        }
    }
}

// ---------------- edge pass 1: stats. 16 lanes/edge, 2 edges/warp -------
__global__ __launch_bounds__(TPB_E) void edge_stats_kernel(int E, int stride) {
    const int lane = threadIdx.x & 31;
    const int hl = lane & 15;
    const int half = lane >> 4;
    const int wid = threadIdx.x >> 5;
    const int gw = blockIdx.x * WPB + wid;

    float s[8], q[8];
#pragma unroll
    for (int j = 0; j < 8; j++) { s[j] = 0.f; q[j] = 0.f; }

    const uint4* __restrict__ U = (const uint4*)g_u;
    const uint4* __restrict__ V = (const uint4*)g_v;
    const int4* __restrict__ EI = (const int4*)g_ei32;

#pragma unroll 2
    for (int it = gw * 2; it < E; it += stride) {
        int4 idx = EI[it >> 1];                 // broadcast: edges it, it+1
        int src = half ? idx.z : idx.x;
        int dst = half ? idx.w : idx.y;
        uint4 ur = U[src * 16 + hl];
        uint4 vr = V[dst * 16 + hl];
        float2 u0 = __half22float2(*(__half2*)&ur.x);
        float2 u1 = __half22float2(*(__half2*)&ur.y);
        float2 u2 = __half22float2(*(__half2*)&ur.z);
        float2 u3 = __half22float2(*(__half2*)&ur.w);
        float2 v0 = __half22float2(*(__half2*)&vr.x);
        float2 v1 = __half22float2(*(__half2*)&vr.y);
        float2 v2 = __half22float2(*(__half2*)&vr.z);
        float2 v3 = __half22float2(*(__half2*)&vr.w);
        float w[8];
        w[0] = u0.x + v0.x; w[1] = u0.y + v0.y;
        w[2] = u1.x + v1.x; w[3] = u1.y + v1.y;
        w[4] = u2.x + v2.x; w[5] = u2.y + v2.y;
        w[6] = u3.x + v3.x; w[7] = u3.y + v3.y;
#pragma unroll
        for (int j = 0; j < 8; j++) {
            s[j] += w[j];
            q[j] = fmaf(w[j], w[j], q[j]);
        }
    }

    __shared__ float red[WPB * 256];
    float* r = red + wid * 256;
    if (half == 0) {
#pragma unroll
        for (int j = 0; j < 8; j++) { r[hl * 8 + j] = s[j]; r[128 + hl * 8 + j] = q[j]; }
    }
    __syncwarp();
    if (half == 1) {
#pragma unroll
        for (int j = 0; j < 8; j++) { r[hl * 8 + j] += s[j]; r[128 + hl * 8 + j] += q[j]; }
    }
    __syncthreads();
    int j = threadIdx.x;
    float t = 0.f;
#pragma unroll
    for (int w = 0; w < WPB; w++) t += red[w * 256 + j];
    g_part[j * NBLK_S + blockIdx.x] = t;
}

// ---------------- parallel partial reduction: 256 blocks ----------------
__global__ __launch_bounds__(256) void reduce_partials_kernel() {
    const int j = blockIdx.x;
    const int t = threadIdx.x;
    float s = 0.f;
    for (int b = t; b < NBLK_S; b += 256) s += g_part[j * NBLK_S + b];
    __shared__ float red[256];
    red[t] = s;
    __syncthreads();
#pragma unroll
    for (int o = 128; o >= 32; o >>= 1) {
        if (t < o) red[t] += red[t + o];
        __syncthreads();
    }
    if (t < 32) {
        float v = red[t];
#pragma unroll
        for (int o = 16; o > 0; o >>= 1) v += __shfl_xor_sync(0xFFFFFFFFu, v, o);
        if (t == 0) g_sums[j] = v;
    }
}

// ---------------- finalize BN affine ------------------------------------
__global__ void finalize_stats_kernel(const float* __restrict__ gamma,
                                      const float* __restrict__ beta,
                                      float invE) {
    int j = threadIdx.x;
    float mean = g_sums[j] * invE;
    float var = fmaf(-mean, mean, g_sums[128 + j] * invE);
    float a = gamma[j] * rsqrtf(var + BN_EPS);
    g_a[j] = a;
    g_c[j] = fmaf(-a, mean, beta[j]);
}

// ---------------- edge pass 2: out. 16 lanes/edge, 2 edges/warp ---------
__global__ __launch_bounds__(TPB_E) void edge_out_kernel(
    const float* __restrict__ W2, const float* __restrict__ b2,
    float* __restrict__ out, int E, int stride) {
    const int lane = threadIdx.x & 31;
    const int hl = lane & 15;
    const int half = lane >> 4;
    const int gw = blockIdx.x * WPB + (threadIdx.x >> 5);

    float a[8], c[8], wa[8], wb[8];
    {
        float4 t0 = *(const float4*)&g_a[hl * 8];
        float4 t1 = *(const float4*)&g_a[hl * 8 + 4];
        a[0]=t0.x; a[1]=t0.y; a[2]=t0.z; a[3]=t0.w;
        a[4]=t1.x; a[5]=t1.y; a[6]=t1.z; a[7]=t1.w;
        t0 = *(const float4*)&g_c[hl * 8];
        t1 = *(const float4*)&g_c[hl * 8 + 4];
        c[0]=t0.x; c[1]=t0.y; c[2]=t0.z; c[3]=t0.w;
        c[4]=t1.x; c[5]=t1.y; c[6]=t1.z; c[7]=t1.w;
        t0 = *(const float4*)&W2[hl * 8];
        t1 = *(const float4*)&W2[hl * 8 + 4];
        wa[0]=t0.x; wa[1]=t0.y; wa[2]=t0.z; wa[3]=t0.w;
        wa[4]=t1.x; wa[5]=t1.y; wa[6]=t1.z; wa[7]=t1.w;
        t0 = *(const float4*)&W2[128 + hl * 8];
        t1 = *(const float4*)&W2[128 + hl * 8 + 4];
        wb[0]=t0.x; wb[1]=t0.y; wb[2]=t0.z; wb[3]=t0.w;
        wb[4]=t1.x; wb[5]=t1.y; wb[6]=t1.z; wb[7]=t1.w;
    }
    const float bz0 = b2[0], bz1 = b2[1];

    const uint4* __restrict__ U = (const uint4*)g_u;
    const uint4* __restrict__ V = (const uint4*)g_v;
    const int4* __restrict__ EI = (const int4*)g_ei32;

#pragma unroll 2
    for (int it = gw * 2; it < E; it += stride) {
        int4 idx = EI[it >> 1];
        int src = half ? idx.z : idx.x;
        int dst = half ? idx.w : idx.y;
        uint4 ur = U[src * 16 + hl];
        uint4 vr = V[dst * 16 + hl];
        float2 u0 = __half22float2(*(__half2*)&ur.x);
        float2 u1 = __half22float2(*(__half2*)&ur.y);
        float2 u2 = __half22float2(*(__half2*)&ur.z);
        float2 u3 = __half22float2(*(__half2*)&ur.w);
        float2 v0 = __half22float2(*(__half2*)&vr.x);
        float2 v1 = __half22float2(*(__half2*)&vr.y);
        float2 v2 = __half22float2(*(__half2*)&vr.z);
        float2 v3 = __half22float2(*(__half2*)&vr.w);
        float w[8];
        w[0] = u0.x + v0.x; w[1] = u0.y + v0.y;
        w[2] = u1.x + v1.x; w[3] = u1.y + v1.y;
        w[4] = u2.x + v2.x; w[5] = u2.y + v2.y;
        w[6] = u3.x + v3.x; w[7] = u3.y + v3.y;
        float p0 = 0.f, p1 = 0.f;
#pragma unroll
        for (int j = 0; j < 8; j++) {
            float rr = fmaxf(fmaf(a[j], w[j], c[j]), 0.f);
            p0 = fmaf(rr, wa[j], p0);
            p1 = fmaf(rr, wb[j], p1);
        }
#pragma unroll
        for (int o = 8; o > 0; o >>= 1) {
            p0 += __shfl_xor_sync(0xFFFFFFFFu, p0, o);
            p1 += __shfl_xor_sync(0xFFFFFFFFu, p1, o);
        }
        if (hl == 0)
            ((float2*)out)[it + half] = make_float2(p0 + bz0, p1 + bz1);
    }
}

// ---------------- launch ------------------------------------------------
extern "C" void kernel_launch(void* const* d_in, const int* in_sizes, int n_in,
                              void* d_out, int out_size) {
    const float* x = (const float*)d_in[0];
    const long long* ei = (const long long*)d_in[1];
    const float* W1 = (const float*)d_in[2];
    // d_in[3] = b1 : cancels inside BatchNorm, unused
    const float* gamma = (const float*)d_in[4];
    const float* beta = (const float*)d_in[5];
    const float* W2 = (const float*)d_in[6];
    const float* b2 = (const float*)d_in[7];

    const int N = in_sizes[0] / DD;
    const int E = in_sizes[1] / 2;
    const int total4 = N * DD / 4;

    detect_idx_kernel<<<1, 1>>>((const int*)ei);
    convert_idx_kernel<<<(E + 255) / 256, 256>>>(ei, E);
    x_to_half_kernel<<<(total4 + 255) / 256, 256>>>(x, total4);
    prep_w1_kernel<<<128, 256>>>(W1);
    dim3 ggrid((N + 127) / 128, 4);
    node_gemm_mma_kernel<<<ggrid, 256>>>(N);
    edge_stats_kernel<<<NBLK_S, TPB_E>>>(E, NBLK_S * WPB * 2);
    reduce_partials_kernel<<<256, 256>>>();
    finalize_stats_kernel<<<1, 128>>>(gamma, beta, 1.0f / (float)E);
    edge_out_kernel<<<NBLK_O, TPB_E>>>(W2, b2, (float*)d_out, E, NBLK_O * WPB * 2);
}